// round 14
// baseline (speedup 1.0000x reference)
#include <cuda_runtime.h>
#include <cuda_fp16.h>
#include <cuda_bf16.h>
#include <math.h>

// ---------------------------------------------------------------------------
// GraphSAGE (3x SAGEConv mean + ReLU, softmax) on GB300 — round 14.
//  * Round-13 chunked agg<->gemm pipeline, FIXED with double buffering:
//    gemm2 -> S2/P2 (separate buffer) so agg1's reads of S1/P1 never race;
//    gemm3 -> S1/P1 (dead by then).  agg_l chunk c gates gemm_{l+1} chunk c.
// ---------------------------------------------------------------------------

#define MAXN 100000
#define MAXE 1600000
#define NCHUNK 4

__device__ int      g_deg[MAXN];
__device__ int      g_rowptr[MAXN + 1];
__device__ int      g_cursor[MAXN];
__device__ int      g_colidx[MAXE];
__device__ float    g_invdeg[MAXN];
__device__ unsigned g_done;                       // tail-block ticket (self-resetting)
__device__ __half   g_S[(size_t)MAXN * 128];      // S1 (w128) / S3 (w64)
__device__ __half   g_P[(size_t)MAXN * 128];      // P1 (w128) / P3 (w64)
__device__ __half   g_SP2[(size_t)MAXN * 128];    // S2 (w64) | P2 (w64)
__device__ __half   g_h[(size_t)MAXN * 128];      // hidden activations, fp16

static __device__ __forceinline__ unsigned su32(const void* p) {
    return (unsigned)__cvta_generic_to_shared(p);
}

#define LDSM_X4(r, a)                                                          \
    asm volatile("ldmatrix.sync.aligned.m8n8.x4.shared.b16 {%0,%1,%2,%3}, [%4];" \
                 : "=r"((r)[0]), "=r"((r)[1]), "=r"((r)[2]), "=r"((r)[3]) : "r"(a))

#define LDSM_X4T(r, a)                                                         \
    asm volatile("ldmatrix.sync.aligned.m8n8.x4.trans.shared.b16 {%0,%1,%2,%3}, [%4];" \
                 : "=r"((r)[0]), "=r"((r)[1]), "=r"((r)[2]), "=r"((r)[3]) : "r"(a))

#define MMA16816(d, a, b0, b1)                                                 \
    asm volatile("mma.sync.aligned.m16n8k16.row.col.f32.f16.f16.f32 "          \
                 "{%0,%1,%2,%3}, {%4,%5,%6,%7}, {%8,%9}, {%0,%1,%2,%3};"       \
                 : "+f"((d)[0]), "+f"((d)[1]), "+f"((d)[2]), "+f"((d)[3])      \
                 : "r"((a)[0]), "r"((a)[1]), "r"((a)[2]), "r"((a)[3]),         \
                   "r"(b0), "r"(b1))

// ---------------------------- CSR construction ----------------------------

__global__ __launch_bounds__(1024) void count_scan_kernel(
    const int* __restrict__ dst, int* __restrict__ deg,
    int* __restrict__ rowptr, int* __restrict__ cursor,
    float* __restrict__ invdeg, int E, int n) {
    int tid = threadIdx.x;

    for (int e = blockIdx.x * 1024 + tid; e < E; e += gridDim.x * 1024)
        atomicAdd(&deg[__ldg(&dst[e])], 1);

    __shared__ bool is_tail;
    __syncthreads();
    if (tid == 0) {
        __threadfence();
        unsigned t = atomicAdd(&g_done, 1);
        is_tail = (t == gridDim.x - 1);
    }
    __syncthreads();
    if (!is_tail) return;
    __threadfence();

    __shared__ int ssum[1024];
    int chunk = (n + 1023) / 1024;
    int lo = tid * chunk;
    int hi = lo + chunk; if (hi > n) hi = n;
    if (lo > n) lo = n;

    int sum = 0;
    for (int i = lo; i < hi; ++i) sum += deg[i];
    ssum[tid] = sum;
    __syncthreads();
    for (int off = 1; off < 1024; off <<= 1) {
        int v = (tid >= off) ? ssum[tid - off] : 0;
        __syncthreads();
        ssum[tid] += v;
        __syncthreads();
    }
    int run = ssum[tid] - sum;
    for (int i = lo; i < hi; ++i) {
        rowptr[i] = run;
        cursor[i] = run;
        float d = (float)deg[i];
        invdeg[i] = 1.0f / fmaxf(d, 1.0f);
        run += deg[i];
    }
    if (tid == 1023) rowptr[n] = ssum[1023];
    if (tid == 0) g_done = 0;
}

__global__ void fill_csr_kernel(const int* __restrict__ src, const int* __restrict__ dst,
                                int* __restrict__ cursor, int* __restrict__ colidx, int E) {
    int e = blockIdx.x * blockDim.x + threadIdx.x;
    if (e < E) {
        int d = __ldg(&dst[e]);
        int p = atomicAdd(&cursor[d], 1);
        colidx[p] = __ldg(&src[e]);
    }
}

// ------------------- aggregation (mean) with fused epilogue ----------------
// warp per node over [i0, i1). t = S[i] + mean_j P[j]  (fp16 pair-tree over
// 4-edge groups, fp32 across groups).  ACT 0: relu->fp16.  ACT 1: softmax->fp32.

template <int D, int ACT>
__global__ void aggregate_ep(const __half* __restrict__ P, const __half* __restrict__ S,
                             const int* __restrict__ rowptr, const int* __restrict__ colidx,
                             const float* __restrict__ invdeg, void* __restrict__ Yv,
                             int i0, int i1) {
    int warp = (blockIdx.x * blockDim.x + threadIdx.x) >> 5;
    int lane = threadIdx.x & 31;
    int nwarps = (gridDim.x * blockDim.x) >> 5;

    for (int i = i0 + warp; i < i1; i += nwarps) {
        int s = __ldg(&rowptr[i]);
        int e = __ldg(&rowptr[i + 1]);
        float inv = __ldg(&invdeg[i]);

        if (D == 128) {
            float4 acc = make_float4(0.f, 0.f, 0.f, 0.f);
            int j = s;
            for (; j + 7 < e; j += 8) {
                int c[8];
#pragma unroll
                for (int q = 0; q < 8; ++q) c[q] = __ldg(&colidx[j + q]);
                uint2 u[8];
#pragma unroll
                for (int q = 0; q < 8; ++q)
                    u[q] = __ldg((const uint2*)(P + (size_t)c[q] * 128) + lane);
                __half2 ax = __hadd2(__hadd2(*(__half2*)&u[0].x, *(__half2*)&u[1].x),
                                     __hadd2(*(__half2*)&u[2].x, *(__half2*)&u[3].x));
                __half2 ay = __hadd2(__hadd2(*(__half2*)&u[0].y, *(__half2*)&u[1].y),
                                     __hadd2(*(__half2*)&u[2].y, *(__half2*)&u[3].y));
                __half2 bx = __hadd2(__hadd2(*(__half2*)&u[4].x, *(__half2*)&u[5].x),
                                     __hadd2(*(__half2*)&u[6].x, *(__half2*)&u[7].x));
                __half2 by = __hadd2(__hadd2(*(__half2*)&u[4].y, *(__half2*)&u[5].y),
                                     __hadd2(*(__half2*)&u[6].y, *(__half2*)&u[7].y));
                float2 f;
                f = __half22float2(ax); acc.x += f.x; acc.y += f.y;
                f = __half22float2(ay); acc.z += f.x; acc.w += f.y;
                f = __half22float2(bx); acc.x += f.x; acc.y += f.y;
                f = __half22float2(by); acc.z += f.x; acc.w += f.y;
            }
            for (; j < e; ++j) {
                int c0 = __ldg(&colidx[j]);
                uint2 u0 = __ldg((const uint2*)(P + (size_t)c0 * 128) + lane);
                float2 a = __half22float2(*(const __half2*)&u0.x);
                float2 b = __half22float2(*(const __half2*)&u0.y);
                acc.x += a.x; acc.y += a.y; acc.z += b.x; acc.w += b.y;
            }
            uint2 us = __ldg((const uint2*)(S + (size_t)i * 128) + lane);
            float2 s0 = __half22float2(*(const __half2*)&us.x);
            float2 s1 = __half22float2(*(const __half2*)&us.y);
            float ox = fmaxf(fmaf(acc.x, inv, s0.x), 0.f);
            float oy = fmaxf(fmaf(acc.y, inv, s0.y), 0.f);
            float oz = fmaxf(fmaf(acc.z, inv, s1.x), 0.f);
            float ow = fmaxf(fmaf(acc.w, inv, s1.y), 0.f);
            __half2 p01 = __floats2half2_rn(ox, oy);
            __half2 p23 = __floats2half2_rn(oz, ow);
            *(uint2*)((__half*)Yv + (size_t)i * 128 + 4 * lane) =
                make_uint2(*(unsigned*)&p01, *(unsigned*)&p23);
        } else {  // D == 64
            float2 acc = make_float2(0.f, 0.f);
            int j = s;
            for (; j + 7 < e; j += 8) {
                int c[8];
#pragma unroll
                for (int q = 0; q < 8; ++q) c[q] = __ldg(&colidx[j + q]);
                unsigned u[8];
#pragma unroll
                for (int q = 0; q < 8; ++q)
                    u[q] = __ldg((const unsigned*)(P + (size_t)c[q] * 64) + lane);
                __half2 a = __hadd2(__hadd2(*(__half2*)&u[0], *(__half2*)&u[1]),
                                    __hadd2(*(__half2*)&u[2], *(__half2*)&u[3]));
                __half2 b = __hadd2(__hadd2(*(__half2*)&u[4], *(__half2*)&u[5]),
                                    __hadd2(*(__half2*)&u[6], *(__half2*)&u[7]));
                float2 f;
                f = __half22float2(a); acc.x += f.x; acc.y += f.y;
                f = __half22float2(b); acc.x += f.x; acc.y += f.y;
            }
            for (; j < e; ++j) {
                int c0 = __ldg(&colidx[j]);
                unsigned u0 = __ldg((const unsigned*)(P + (size_t)c0 * 64) + lane);
                float2 f = __half22float2(*(const __half2*)&u0);
                acc.x += f.x; acc.y += f.y;
            }
            unsigned us = __ldg((const unsigned*)(S + (size_t)i * 64) + lane);
            float2 sf = __half22float2(*(const __half2*)&us);
            float tx = fmaf(acc.x, inv, sf.x);
            float ty = fmaf(acc.y, inv, sf.y);
            if (ACT == 0) {
                __half2 hp = __floats2half2_rn(fmaxf(tx, 0.f), fmaxf(ty, 0.f));
                *(unsigned*)((__half*)Yv + (size_t)i * 64 + 2 * lane) = *(unsigned*)&hp;
            } else {
                float m = fmaxf(tx, ty);
#pragma unroll
                for (int o = 16; o; o >>= 1) m = fmaxf(m, __shfl_xor_sync(0xffffffffu, m, o));
                float ex = __expf(tx - m);
                float ey = __expf(ty - m);
                float sm = ex + ey;
#pragma unroll
                for (int o = 16; o; o >>= 1) sm += __shfl_xor_sync(0xffffffffu, sm, o);
                float rinv = 1.0f / sm;
                ((float2*)((float*)Yv + (size_t)i * 64))[lane] = make_float2(ex * rinv, ey * rinv);
            }
        }
    }
}

// ----------------------- tensor-core projection GEMM -----------------------
// 2-phase split: C = Ah*Wh + Ah*Wl (fp32 accum). A plain fp16 (width K);
// sB holds Wh rows [0..K) and Wl rows [K..2K). Both output halves fp16.

template <int K, bool PREHALF>
__global__ __launch_bounds__(256, 2) void gemm_mma(
    const void* __restrict__ Av, const float* __restrict__ Ws,
    const float* __restrict__ Wn, const float* __restrict__ bias,
    __half* __restrict__ S, __half* __restrict__ P,
    int n, int HF, int nh) {
    constexpr int LDA = K + 8;
    constexpr int LDB = 136;
    extern __shared__ __half smh[];
    __half* sA = smh;                 // [64][LDA]
    __half* sB = smh + 64 * LDA;      // [2K][LDB]

    int tid = threadIdx.x;
    int h = blockIdx.x % nh;
    int colbase = h * 128;
    int t0 = blockIdx.x / nh;
    int tstep = gridDim.x / nh;

    for (int idx = tid; idx < K * 128; idx += 256) {
        int k = idx >> 7, c = idx & 127;
        int gc = colbase + c;
        float w = (gc < HF) ? __ldg(&Ws[k * HF + gc]) : __ldg(&Wn[k * HF + gc - HF]);
        __half wh = __float2half_rn(w);
        sB[k * LDB + c] = wh;
        sB[(K + k) * LDB + c] = __float2half_rn(w - __half2float(wh));
    }

    int lane = tid & 31;
    int warp = tid >> 5;
    int wm = warp & 3;
    int wnh = warp >> 2;

    int arow = wm * 16 + (lane & 15);
    int acolsel = (lane >> 4) * 8;
    int brow = lane & 15;
    int bcol = wnh * 64 + (lane >> 4) * 8;

    float2 binit[8];
#pragma unroll
    for (int nt = 0; nt < 8; ++nt) {
        int gc = colbase + wnh * 64 + nt * 8 + (lane & 3) * 2;
        float b0 = 0.f, b1 = 0.f;
        if (gc < HF) { b0 = __ldg(&bias[gc]); b1 = __ldg(&bias[gc + 1]); }
        binit[nt] = make_float2(b0, b1);
    }

    int ntiles = (n + 63) >> 6;
    for (int t = t0; t < ntiles; t += tstep) {
        int row0g = t * 64;
        __syncthreads();

        if (PREHALF) {
            constexpr int CPR = K / 8;
            const __half* A = (const __half*)Av;
            for (int idx = tid; idx < 64 * CPR; idx += 256) {
                int r = idx / CPR, c = idx % CPR;
                int gr = row0g + r;
                uint4 v = make_uint4(0u, 0u, 0u, 0u);
                if (gr < n) v = __ldg((const uint4*)(A + (size_t)gr * K) + c);
                *(uint4*)&sA[r * LDA + c * 8] = v;
            }
        } else {
            const float* A = (const float*)Av;
            for (int idx = tid; idx < 64 * (K / 4); idx += 256) {
                int r  = idx / (K / 4);
                int k4 = idx % (K / 4);
                int gr = row0g + r;
                float4 v = make_float4(0.f, 0.f, 0.f, 0.f);
                if (gr < n) v = __ldg((const float4*)(A + (size_t)gr * K) + k4);
                __half2* ph = (__half2*)&sA[r * LDA + k4 * 4];
                ph[0] = __floats2half2_rn(v.x, v.y);
                ph[1] = __floats2half2_rn(v.z, v.w);
            }
        }
        __syncthreads();

        float acc[8][4];
#pragma unroll
        for (int nt = 0; nt < 8; ++nt) {
            acc[nt][0] = binit[nt].x; acc[nt][1] = binit[nt].y;
            acc[nt][2] = binit[nt].x; acc[nt][3] = binit[nt].y;
        }

#pragma unroll
        for (int k16 = 0; k16 < K; k16 += 16) {
            unsigned ah[4];
            LDSM_X4(ah, su32(&sA[arow * LDA + k16 + acolsel]));
#pragma unroll
            for (int tt = 0; tt < 4; ++tt) {
                unsigned bh[4], bl[4];
                LDSM_X4T(bh, su32(&sB[(k16 + brow) * LDB + bcol + tt * 16]));
                MMA16816(acc[tt * 2],     ah, bh[0], bh[1]);
                MMA16816(acc[tt * 2 + 1], ah, bh[2], bh[3]);
                LDSM_X4T(bl, su32(&sB[(K + k16 + brow) * LDB + bcol + tt * 16]));
                MMA16816(acc[tt * 2],     ah, bl[0], bl[1]);
                MMA16816(acc[tt * 2 + 1], ah, bl[2], bl[3]);
            }
        }

        int r0 = row0g + wm * 16 + (lane >> 2);
#pragma unroll
        for (int nt = 0; nt < 8; ++nt) {
            int gc = colbase + wnh * 64 + nt * 8 + (lane & 3) * 2;
            __half* dstp = (gc < HF) ? S : P;
            int col = (gc < HF) ? gc : gc - HF;
            if (r0 < n)
                *(__half2*)(dstp + (size_t)r0 * HF + col) =
                    __floats2half2_rn(acc[nt][0], acc[nt][1]);
            if (r0 + 8 < n)
                *(__half2*)(dstp + (size_t)(r0 + 8) * HF + col) =
                    __floats2half2_rn(acc[nt][2], acc[nt][3]);
        }
    }
}

// ---------------------------------------------------------------------------

extern "C" void kernel_launch(void* const* d_in, const int* in_sizes, int n_in,
                              void* d_out, int out_size) {
    const float* x   = (const float*)d_in[0];
    const int*   src = (const int*)d_in[1];
    const int*   dst = (const int*)d_in[2];
    const float* ws1 = (const float*)d_in[3];
    const float* wn1 = (const float*)d_in[4];
    const float* b1  = (const float*)d_in[5];
    const float* ws2 = (const float*)d_in[6];
    const float* wn2 = (const float*)d_in[7];
    const float* b2  = (const float*)d_in[8];
    const float* ws3 = (const float*)d_in[9];
    const float* wn3 = (const float*)d_in[10];
    const float* b3  = (const float*)d_in[11];
    float* out = (float*)d_out;

    int N = in_sizes[0] / 128;
    int E = in_sizes[1];

    int *deg, *rowptr, *cursor, *colidx;
    float *invdeg;
    __half *S1, *P1, *SP2, *hs;
    cudaGetSymbolAddress((void**)&deg,    g_deg);
    cudaGetSymbolAddress((void**)&rowptr, g_rowptr);
    cudaGetSymbolAddress((void**)&cursor, g_cursor);
    cudaGetSymbolAddress((void**)&colidx, g_colidx);
    cudaGetSymbolAddress((void**)&invdeg, g_invdeg);
    cudaGetSymbolAddress((void**)&S1,     g_S);
    cudaGetSymbolAddress((void**)&P1,     g_P);
    cudaGetSymbolAddress((void**)&SP2,    g_SP2);
    cudaGetSymbolAddress((void**)&hs,     g_h);

    // layer-2 outputs (width 64) live in their own buffer: no alias with S1/P1
    __half* S2 = SP2;                          // MAXN*64 halves
    __half* P2 = SP2 + (size_t)MAXN * 64;      // MAXN*64 halves
    // layer-3 outputs reuse S1/P1 (dead after agg1, which finishes before gemm3)
    __half* S3 = S1;
    __half* P3 = P1;

    const int SMEM_K128 = (64 * (128 + 8) + 2 * 128 * 136) * 2;  // 87040
    const int SMEM_K64  = (64 * (64 + 8) + 2 * 64 * 136) * 2;    // 44032
    cudaFuncSetAttribute((const void*)gemm_mma<128, false>,
                         cudaFuncAttributeMaxDynamicSharedMemorySize, SMEM_K128);
    cudaFuncSetAttribute((const void*)gemm_mma<128, true>,
                         cudaFuncAttributeMaxDynamicSharedMemorySize, SMEM_K128);
    cudaFuncSetAttribute((const void*)gemm_mma<64, true>,
                         cudaFuncAttributeMaxDynamicSharedMemorySize, SMEM_K64);

    static cudaStream_t s_csr = 0, s_agg = 0;
    static cudaEvent_t e_fork = 0, e_join = 0, eg1 = 0, eg2 = 0, eg3 = 0, e_done = 0;
    static cudaEvent_t ea1[NCHUNK], ea2[NCHUNK];
    if (!s_csr) {
        cudaStreamCreateWithFlags(&s_csr, cudaStreamNonBlocking);
        cudaStreamCreateWithFlags(&s_agg, cudaStreamNonBlocking);
        cudaEventCreateWithFlags(&e_fork, cudaEventDisableTiming);
        cudaEventCreateWithFlags(&e_join, cudaEventDisableTiming);
        cudaEventCreateWithFlags(&eg1, cudaEventDisableTiming);
        cudaEventCreateWithFlags(&eg2, cudaEventDisableTiming);
        cudaEventCreateWithFlags(&eg3, cudaEventDisableTiming);
        cudaEventCreateWithFlags(&e_done, cudaEventDisableTiming);
        for (int c = 0; c < NCHUNK; ++c) {
            cudaEventCreateWithFlags(&ea1[c], cudaEventDisableTiming);
            cudaEventCreateWithFlags(&ea2[c], cudaEventDisableTiming);
        }
    }

    // chunk boundaries (64-aligned)
    int Nc = (((N + NCHUNK - 1) / NCHUNK + 63) / 64) * 64;
    int c0[NCHUNK], c1[NCHUNK];
    for (int c = 0; c < NCHUNK; ++c) {
        c0[c] = c * Nc;
        c1[c] = min(N, c0[c] + Nc);
        if (c0[c] > N) c0[c] = N;
    }

    // ---- fork: CSR build on side stream ----
    cudaEventRecord(e_fork, 0);
    cudaStreamWaitEvent(s_csr, e_fork, 0);
    cudaMemsetAsync(deg, 0, N * sizeof(int), s_csr);
    count_scan_kernel<<<296, 1024, 0, s_csr>>>(dst, deg, rowptr, cursor, invdeg, E, N);
    fill_csr_kernel<<<(E + 255) / 256, 256, 0, s_csr>>>(src, dst, cursor, colidx, E);
    cudaEventRecord(e_join, s_csr);

    // ---- layer-1 GEMM (full machine): X -> S1,P1 (w128) ----
    gemm_mma<128, false><<<296, 256, SMEM_K128>>>(x, ws1, wn1, b1, S1, P1, N, 128, 2);
    cudaEventRecord(eg1, 0);

    // ---- agg1 chunks (reads S1,P1 -> hs w128) overlap gemm2 chunks
    //      (reads hs -> writes S2,P2: DIFFERENT buffer, no race) ----
    cudaStreamWaitEvent(s_agg, e_join, 0);
    cudaStreamWaitEvent(s_agg, eg1, 0);
    for (int c = 0; c < NCHUNK; ++c) {
        aggregate_ep<128, 0><<<1024, 256, 0, s_agg>>>(P1, S1, rowptr, colidx, invdeg,
                                                      hs, c0[c], c1[c]);
        cudaEventRecord(ea1[c], s_agg);
    }
    for (int c = 0; c < NCHUNK; ++c) {
        cudaStreamWaitEvent(0, ea1[c], 0);
        int nr = c1[c] - c0[c];
        if (nr <= 0) continue;
        gemm_mma<128, true><<<148, 256, SMEM_K128>>>(
            hs + (size_t)c0[c] * 128, ws2, wn2, b2,
            S2 + (size_t)c0[c] * 64, P2 + (size_t)c0[c] * 64, nr, 64, 1);
    }
    cudaEventRecord(eg2, 0);

    // ---- agg2 chunks (reads S2,P2 -> hs w64) overlap gemm3 chunks
    //      (reads hs -> writes S3,P3 = S1,P1: dead after agg1) ----
    cudaStreamWaitEvent(s_agg, eg2, 0);
    for (int c = 0; c < NCHUNK; ++c) {
        aggregate_ep<64, 0><<<1024, 256, 0, s_agg>>>(P2, S2, rowptr, colidx, invdeg,
                                                     hs, c0[c], c1[c]);
        cudaEventRecord(ea2[c], s_agg);
    }
    for (int c = 0; c < NCHUNK; ++c) {
        cudaStreamWaitEvent(0, ea2[c], 0);
        int nr = c1[c] - c0[c];
        if (nr <= 0) continue;
        gemm_mma<64, true><<<148, 256, SMEM_K64>>>(
            hs + (size_t)c0[c] * 64, ws3, wn3, b3,
            S3 + (size_t)c0[c] * 64, P3 + (size_t)c0[c] * 64, nr, 64, 1);
    }
    cudaEventRecord(eg3, 0);

    // ---- final: softmax aggregation (full) ----
    cudaStreamWaitEvent(s_agg, eg3, 0);
    aggregate_ep<64, 1><<<2048, 256, 0, s_agg>>>(P3, S3, rowptr, colidx, invdeg,
                                                 out, 0, N);
    cudaEventRecord(e_done, s_agg);
    cudaStreamWaitEvent(0, e_done, 0);
}

// round 16
// speedup vs baseline: 1.1417x; 1.1417x over previous
#include <cuda_runtime.h>
#include <cuda_fp16.h>
#include <cuda_bf16.h>
#include <math.h>

// ---------------------------------------------------------------------------
// GraphSAGE (3x SAGEConv mean + ReLU, softmax) on GB300 — round 16.
//  * tcgen05 unavailable (ptxas targets sm_103 without 'a') — mma.sync stays.
//  * GEMM M-tile 64 -> 128 rows: B ldmatrix fragments amortized over 2x rows
//    (LDSM/row -44%) to attack the measured L1-boundedness of gemm1.
//  * Everything else identical to round 12 (best flat schedule, 419.8us).
// ---------------------------------------------------------------------------

#define MAXN 100000
#define MAXE 1600000

__device__ int      g_deg[MAXN];
__device__ int      g_rowptr[MAXN + 1];
__device__ int      g_cursor[MAXN];
__device__ int      g_colidx[MAXE];
__device__ float    g_invdeg[MAXN];
__device__ unsigned g_done;                       // tail-block ticket
__device__ __half   g_S[(size_t)MAXN * 128];      // self-projection (+bias), fp16
__device__ __half   g_P[(size_t)MAXN * 128];      // neighbor-projection, fp16
__device__ __half   g_h[(size_t)MAXN * 128];      // hidden activations, fp16

static __device__ __forceinline__ unsigned su32(const void* p) {
    return (unsigned)__cvta_generic_to_shared(p);
}

#define LDSM_X4(r, a)                                                          \
    asm volatile("ldmatrix.sync.aligned.m8n8.x4.shared.b16 {%0,%1,%2,%3}, [%4];" \
                 : "=r"((r)[0]), "=r"((r)[1]), "=r"((r)[2]), "=r"((r)[3]) : "r"(a))

#define LDSM_X4T(r, a)                                                         \
    asm volatile("ldmatrix.sync.aligned.m8n8.x4.trans.shared.b16 {%0,%1,%2,%3}, [%4];" \
                 : "=r"((r)[0]), "=r"((r)[1]), "=r"((r)[2]), "=r"((r)[3]) : "r"(a))

#define MMA16816(d, a, b0, b1)                                                 \
    asm volatile("mma.sync.aligned.m16n8k16.row.col.f32.f16.f16.f32 "          \
                 "{%0,%1,%2,%3}, {%4,%5,%6,%7}, {%8,%9}, {%0,%1,%2,%3};"       \
                 : "+f"((d)[0]), "+f"((d)[1]), "+f"((d)[2]), "+f"((d)[3])      \
                 : "r"((a)[0]), "r"((a)[1]), "r"((a)[2]), "r"((a)[3]),         \
                   "r"(b0), "r"(b1))

// ---------------------------- CSR construction ----------------------------

__global__ __launch_bounds__(1024) void count_scan_kernel(
    const int* __restrict__ dst, int* __restrict__ deg,
    int* __restrict__ rowptr, int* __restrict__ cursor,
    float* __restrict__ invdeg, int E, int n) {
    int tid = threadIdx.x;

    for (int e = blockIdx.x * 1024 + tid; e < E; e += gridDim.x * 1024)
        atomicAdd(&deg[__ldg(&dst[e])], 1);

    __shared__ bool is_tail;
    __syncthreads();
    if (tid == 0) {
        __threadfence();
        unsigned t = atomicAdd(&g_done, 1);
        is_tail = (t == gridDim.x - 1);
    }
    __syncthreads();
    if (!is_tail) return;
    __threadfence();

    __shared__ int ssum[1024];
    int chunk = (n + 1023) / 1024;
    int lo = tid * chunk;
    int hi = lo + chunk; if (hi > n) hi = n;
    if (lo > n) lo = n;

    int sum = 0;
    for (int i = lo; i < hi; ++i) sum += deg[i];
    ssum[tid] = sum;
    __syncthreads();
    for (int off = 1; off < 1024; off <<= 1) {
        int v = (tid >= off) ? ssum[tid - off] : 0;
        __syncthreads();
        ssum[tid] += v;
        __syncthreads();
    }
    int run = ssum[tid] - sum;
    for (int i = lo; i < hi; ++i) {
        rowptr[i] = run;
        cursor[i] = run;
        float d = (float)deg[i];
        invdeg[i] = 1.0f / fmaxf(d, 1.0f);
        run += deg[i];
    }
    if (tid == 1023) rowptr[n] = ssum[1023];
    if (tid == 0) g_done = 0;
}

__global__ void fill_csr_kernel(const int* __restrict__ src, const int* __restrict__ dst,
                                int* __restrict__ cursor, int* __restrict__ colidx, int E) {
    int e = blockIdx.x * blockDim.x + threadIdx.x;
    if (e < E) {
        int d = __ldg(&dst[e]);
        int p = atomicAdd(&cursor[d], 1);
        colidx[p] = __ldg(&src[e]);
    }
}

// ------------------- aggregation (round-12, unchanged) ---------------------

template <int D, int ACT>
__global__ void aggregate_ep(const __half* __restrict__ P, const __half* __restrict__ S,
                             const int* __restrict__ rowptr, const int* __restrict__ colidx,
                             const float* __restrict__ invdeg, void* __restrict__ Yv, int n) {
    int warp = (blockIdx.x * blockDim.x + threadIdx.x) >> 5;
    int lane = threadIdx.x & 31;
    int nwarps = (gridDim.x * blockDim.x) >> 5;

    for (int i = warp; i < n; i += nwarps) {
        int s = __ldg(&rowptr[i]);
        int e = __ldg(&rowptr[i + 1]);
        float inv = __ldg(&invdeg[i]);

        if (D == 128) {
            float4 acc = make_float4(0.f, 0.f, 0.f, 0.f);
            int j = s;
            for (; j + 7 < e; j += 8) {
                int c[8];
#pragma unroll
                for (int q = 0; q < 8; ++q) c[q] = __ldg(&colidx[j + q]);
                uint2 u[8];
#pragma unroll
                for (int q = 0; q < 8; ++q)
                    u[q] = __ldg((const uint2*)(P + (size_t)c[q] * 128) + lane);
                __half2 ax = __hadd2(__hadd2(*(__half2*)&u[0].x, *(__half2*)&u[1].x),
                                     __hadd2(*(__half2*)&u[2].x, *(__half2*)&u[3].x));
                __half2 ay = __hadd2(__hadd2(*(__half2*)&u[0].y, *(__half2*)&u[1].y),
                                     __hadd2(*(__half2*)&u[2].y, *(__half2*)&u[3].y));
                __half2 bx = __hadd2(__hadd2(*(__half2*)&u[4].x, *(__half2*)&u[5].x),
                                     __hadd2(*(__half2*)&u[6].x, *(__half2*)&u[7].x));
                __half2 by = __hadd2(__hadd2(*(__half2*)&u[4].y, *(__half2*)&u[5].y),
                                     __hadd2(*(__half2*)&u[6].y, *(__half2*)&u[7].y));
                float2 f;
                f = __half22float2(ax); acc.x += f.x; acc.y += f.y;
                f = __half22float2(ay); acc.z += f.x; acc.w += f.y;
                f = __half22float2(bx); acc.x += f.x; acc.y += f.y;
                f = __half22float2(by); acc.z += f.x; acc.w += f.y;
            }
            for (; j < e; ++j) {
                int c0 = __ldg(&colidx[j]);
                uint2 u0 = __ldg((const uint2*)(P + (size_t)c0 * 128) + lane);
                float2 a = __half22float2(*(const __half2*)&u0.x);
                float2 b = __half22float2(*(const __half2*)&u0.y);
                acc.x += a.x; acc.y += a.y; acc.z += b.x; acc.w += b.y;
            }
            uint2 us = __ldg((const uint2*)(S + (size_t)i * 128) + lane);
            float2 s0 = __half22float2(*(const __half2*)&us.x);
            float2 s1 = __half22float2(*(const __half2*)&us.y);
            float ox = fmaxf(fmaf(acc.x, inv, s0.x), 0.f);
            float oy = fmaxf(fmaf(acc.y, inv, s0.y), 0.f);
            float oz = fmaxf(fmaf(acc.z, inv, s1.x), 0.f);
            float ow = fmaxf(fmaf(acc.w, inv, s1.y), 0.f);
            __half2 p01 = __floats2half2_rn(ox, oy);
            __half2 p23 = __floats2half2_rn(oz, ow);
            *(uint2*)((__half*)Yv + (size_t)i * 128 + 4 * lane) =
                make_uint2(*(unsigned*)&p01, *(unsigned*)&p23);
        } else {  // D == 64
            float2 acc = make_float2(0.f, 0.f);
            int j = s;
            for (; j + 7 < e; j += 8) {
                int c[8];
#pragma unroll
                for (int q = 0; q < 8; ++q) c[q] = __ldg(&colidx[j + q]);
                unsigned u[8];
#pragma unroll
                for (int q = 0; q < 8; ++q)
                    u[q] = __ldg((const unsigned*)(P + (size_t)c[q] * 64) + lane);
                __half2 a = __hadd2(__hadd2(*(__half2*)&u[0], *(__half2*)&u[1]),
                                    __hadd2(*(__half2*)&u[2], *(__half2*)&u[3]));
                __half2 b = __hadd2(__hadd2(*(__half2*)&u[4], *(__half2*)&u[5]),
                                    __hadd2(*(__half2*)&u[6], *(__half2*)&u[7]));
                float2 f;
                f = __half22float2(a); acc.x += f.x; acc.y += f.y;
                f = __half22float2(b); acc.x += f.x; acc.y += f.y;
            }
            for (; j < e; ++j) {
                int c0 = __ldg(&colidx[j]);
                unsigned u0 = __ldg((const unsigned*)(P + (size_t)c0 * 64) + lane);
                float2 f = __half22float2(*(const __half2*)&u0);
                acc.x += f.x; acc.y += f.y;
            }
            unsigned us = __ldg((const unsigned*)(S + (size_t)i * 64) + lane);
            float2 sf = __half22float2(*(const __half2*)&us);
            float tx = fmaf(acc.x, inv, sf.x);
            float ty = fmaf(acc.y, inv, sf.y);
            if (ACT == 0) {
                __half2 hp = __floats2half2_rn(fmaxf(tx, 0.f), fmaxf(ty, 0.f));
                *(unsigned*)((__half*)Yv + (size_t)i * 64 + 2 * lane) = *(unsigned*)&hp;
            } else {
                float m = fmaxf(tx, ty);
#pragma unroll
                for (int o = 16; o; o >>= 1) m = fmaxf(m, __shfl_xor_sync(0xffffffffu, m, o));
                float ex = __expf(tx - m);
                float ey = __expf(ty - m);
                float sm = ex + ey;
#pragma unroll
                for (int o = 16; o; o >>= 1) sm += __shfl_xor_sync(0xffffffffu, sm, o);
                float rinv = 1.0f / sm;
                ((float2*)((float*)Yv + (size_t)i * 64))[lane] = make_float2(ex * rinv, ey * rinv);
            }
        }
    }
}

// ----------------------- tensor-core projection GEMM -----------------------
// M-tile = 128 rows. 8 warps = 4 m-strips(32 rows = 2 MMA subtiles) x 2
// n-halves(64). B fragments amortized over 32 rows. 2-phase: Ah*Wh + Ah*Wl.

template <int K, bool PREHALF>
__global__ __launch_bounds__(256, 2) void gemm_mma(
    const void* __restrict__ Av, const float* __restrict__ Ws,
    const float* __restrict__ Wn, const float* __restrict__ bias,
    __half* __restrict__ S, __half* __restrict__ P,
    int n, int HF, int nh) {
    constexpr int LDA = K + 8;
    constexpr int LDB = 136;
    extern __shared__ __half smh[];
    __half* sA = smh;                 // [128][LDA]
    __half* sB = smh + 128 * LDA;     // [2K][LDB]  (Wh rows, Wl rows)

    int tid = threadIdx.x;
    int h = blockIdx.x % nh;
    int colbase = h * 128;
    int t0 = blockIdx.x / nh;
    int tstep = gridDim.x / nh;

    for (int idx = tid; idx < K * 128; idx += 256) {
        int k = idx >> 7, c = idx & 127;
        int gc = colbase + c;
        float w = (gc < HF) ? __ldg(&Ws[k * HF + gc]) : __ldg(&Wn[k * HF + gc - HF]);
        __half wh = __float2half_rn(w);
        sB[k * LDB + c] = wh;
        sB[(K + k) * LDB + c] = __float2half_rn(w - __half2float(wh));
    }

    int lane = tid & 31;
    int warp = tid >> 5;
    int wm = warp & 3;
    int wnh = warp >> 2;

    int arow0 = wm * 32 + (lane & 15);
    int acolsel = (lane >> 4) * 8;
    int brow = lane & 15;
    int bcol = wnh * 64 + (lane >> 4) * 8;

    float2 binit[8];
#pragma unroll
    for (int nt = 0; nt < 8; ++nt) {
        int gc = colbase + wnh * 64 + nt * 8 + (lane & 3) * 2;
        float b0 = 0.f, b1 = 0.f;
        if (gc < HF) { b0 = __ldg(&bias[gc]); b1 = __ldg(&bias[gc + 1]); }
        binit[nt] = make_float2(b0, b1);
    }

    int ntiles = (n + 127) >> 7;
    for (int t = t0; t < ntiles; t += tstep) {
        int row0g = t * 128;
        __syncthreads();

        if (PREHALF) {
            constexpr int CPR = K / 8;   // uint4 chunks per row
            const __half* A = (const __half*)Av;
            for (int idx = tid; idx < 128 * CPR; idx += 256) {
                int r = idx / CPR, c = idx % CPR;
                int gr = row0g + r;
                uint4 v = make_uint4(0u, 0u, 0u, 0u);
                if (gr < n) v = __ldg((const uint4*)(A + (size_t)gr * K) + c);
                *(uint4*)&sA[r * LDA + c * 8] = v;
            }
        } else {
            const float* A = (const float*)Av;
            for (int idx = tid; idx < 128 * (K / 4); idx += 256) {
                int r  = idx / (K / 4);
                int k4 = idx % (K / 4);
                int gr = row0g + r;
                float4 v = make_float4(0.f, 0.f, 0.f, 0.f);
                if (gr < n) v = __ldg((const float4*)(A + (size_t)gr * K) + k4);
                __half2* ph = (__half2*)&sA[r * LDA + k4 * 4];
                ph[0] = __floats2half2_rn(v.x, v.y);
                ph[1] = __floats2half2_rn(v.z, v.w);
            }
        }
        __syncthreads();

        float acc[2][8][4];
#pragma unroll
        for (int st = 0; st < 2; ++st)
#pragma unroll
            for (int nt = 0; nt < 8; ++nt) {
                acc[st][nt][0] = binit[nt].x; acc[st][nt][1] = binit[nt].y;
                acc[st][nt][2] = binit[nt].x; acc[st][nt][3] = binit[nt].y;
            }

        // 2-phase K sweep; B fragments shared across both 16-row subtiles
#pragma unroll
        for (int k16 = 0; k16 < K; k16 += 16) {
            unsigned a0[4], a1[4];
            LDSM_X4(a0, su32(&sA[arow0 * LDA + k16 + acolsel]));
            LDSM_X4(a1, su32(&sA[(arow0 + 16) * LDA + k16 + acolsel]));
#pragma unroll
            for (int tt = 0; tt < 4; ++tt) {
                unsigned bh[4], bl[4];
                LDSM_X4T(bh, su32(&sB[(k16 + brow) * LDB + bcol + tt * 16]));
                MMA16816(acc[0][tt * 2],     a0, bh[0], bh[1]);
                MMA16816(acc[0][tt * 2 + 1], a0, bh[2], bh[3]);
                MMA16816(acc[1][tt * 2],     a1, bh[0], bh[1]);
                MMA16816(acc[1][tt * 2 + 1], a1, bh[2], bh[3]);
                LDSM_X4T(bl, su32(&sB[(K + k16 + brow) * LDB + bcol + tt * 16]));
                MMA16816(acc[0][tt * 2],     a0, bl[0], bl[1]);
                MMA16816(acc[0][tt * 2 + 1], a0, bl[2], bl[3]);
                MMA16816(acc[1][tt * 2],     a1, bl[0], bl[1]);
                MMA16816(acc[1][tt * 2 + 1], a1, bl[2], bl[3]);
            }
        }

        // epilogue: both halves fp16
#pragma unroll
        for (int st = 0; st < 2; ++st) {
            int r0 = row0g + wm * 32 + st * 16 + (lane >> 2);
#pragma unroll
            for (int nt = 0; nt < 8; ++nt) {
                int gc = colbase + wnh * 64 + nt * 8 + (lane & 3) * 2;
                __half* dstp = (gc < HF) ? S : P;
                int col = (gc < HF) ? gc : gc - HF;
                if (r0 < n)
                    *(__half2*)(dstp + (size_t)r0 * HF + col) =
                        __floats2half2_rn(acc[st][nt][0], acc[st][nt][1]);
                if (r0 + 8 < n)
                    *(__half2*)(dstp + (size_t)(r0 + 8) * HF + col) =
                        __floats2half2_rn(acc[st][nt][2], acc[st][nt][3]);
            }
        }
    }
}

// ---------------------------------------------------------------------------

extern "C" void kernel_launch(void* const* d_in, const int* in_sizes, int n_in,
                              void* d_out, int out_size) {
    const float* x   = (const float*)d_in[0];
    const int*   src = (const int*)d_in[1];
    const int*   dst = (const int*)d_in[2];
    const float* ws1 = (const float*)d_in[3];
    const float* wn1 = (const float*)d_in[4];
    const float* b1  = (const float*)d_in[5];
    const float* ws2 = (const float*)d_in[6];
    const float* wn2 = (const float*)d_in[7];
    const float* b2  = (const float*)d_in[8];
    const float* ws3 = (const float*)d_in[9];
    const float* wn3 = (const float*)d_in[10];
    const float* b3  = (const float*)d_in[11];
    float* out = (float*)d_out;

    int N = in_sizes[0] / 128;
    int E = in_sizes[1];

    int *deg, *rowptr, *cursor, *colidx;
    float *invdeg;
    __half *Sb, *Pb, *hs;
    cudaGetSymbolAddress((void**)&deg,    g_deg);
    cudaGetSymbolAddress((void**)&rowptr, g_rowptr);
    cudaGetSymbolAddress((void**)&cursor, g_cursor);
    cudaGetSymbolAddress((void**)&colidx, g_colidx);
    cudaGetSymbolAddress((void**)&invdeg, g_invdeg);
    cudaGetSymbolAddress((void**)&Sb,     g_S);
    cudaGetSymbolAddress((void**)&Pb,     g_P);
    cudaGetSymbolAddress((void**)&hs,     g_h);

    // smem: K=128 -> 128*136*2 + 256*136*2 = 34816 + 69632 = 104448
    //       K=64  -> 128*72*2  + 128*136*2 = 18432 + 34816 =  53248
    const int SMEM_K128 = (128 * (128 + 8) + 2 * 128 * 136) * 2;
    const int SMEM_K64  = (128 * (64 + 8) + 2 * 64 * 136) * 2;
    cudaFuncSetAttribute((const void*)gemm_mma<128, false>,
                         cudaFuncAttributeMaxDynamicSharedMemorySize, SMEM_K128);
    cudaFuncSetAttribute((const void*)gemm_mma<128, true>,
                         cudaFuncAttributeMaxDynamicSharedMemorySize, SMEM_K128);
    cudaFuncSetAttribute((const void*)gemm_mma<64, true>,
                         cudaFuncAttributeMaxDynamicSharedMemorySize, SMEM_K64);

    static cudaStream_t s_csr = 0;
    static cudaEvent_t e_fork = 0, e_join = 0;
    if (!s_csr) {
        cudaStreamCreateWithFlags(&s_csr, cudaStreamNonBlocking);
        cudaEventCreateWithFlags(&e_fork, cudaEventDisableTiming);
        cudaEventCreateWithFlags(&e_join, cudaEventDisableTiming);
    }

    // ---- fork: CSR build on side stream ----
    cudaEventRecord(e_fork, 0);
    cudaStreamWaitEvent(s_csr, e_fork, 0);
    cudaMemsetAsync(deg, 0, N * sizeof(int), s_csr);
    count_scan_kernel<<<296, 1024, 0, s_csr>>>(dst, deg, rowptr, cursor, invdeg, E, N);
    fill_csr_kernel<<<(E + 255) / 256, 256, 0, s_csr>>>(src, dst, cursor, colidx, E);
    cudaEventRecord(e_join, s_csr);

    // ---- layer-1 GEMM (fp32 X, 2 column halves) ----
    gemm_mma<128, false><<<296, 256, SMEM_K128>>>(x, ws1, wn1, b1, Sb, Pb, N, 128, 2);
    cudaStreamWaitEvent(0, e_join, 0);

    const int AGG_BLOCKS = 2048;

    // ---- layer 1 ----
    aggregate_ep<128, 0><<<AGG_BLOCKS, 256>>>(Pb, Sb, rowptr, colidx, invdeg, hs, N);
    // ---- layer 2 ----
    gemm_mma<128, true><<<296, 256, SMEM_K128>>>(hs, ws2, wn2, b2, Sb, Pb, N, 64, 1);
    aggregate_ep<64, 0><<<AGG_BLOCKS, 256>>>(Pb, Sb, rowptr, colidx, invdeg, hs, N);
    // ---- layer 3 ----
    gemm_mma<64, true><<<296, 256, SMEM_K64>>>(hs, ws3, wn3, b3, Sb, Pb, N, 64, 1);
    aggregate_ep<64, 1><<<AGG_BLOCKS, 256>>>(Pb, Sb, rowptr, colidx, invdeg, out, N);
}